// round 8
// baseline (speedup 1.0000x reference)
#include <cuda_runtime.h>
#include <cuda_bf16.h>
#include <cstdint>
#include <math.h>

// ---------------- problem constants ----------------
#define BS_      16
#define LQ_      1000
#define NROWS    (BS_*LQ_)         // 16000
#define EMBED    256
#define NHEADS   8
#define HDIM     32
#define NLOGIT   384               // 256 offset cols + 128 attn-prob cols
#define LV_      13294
#define NPTS     (NROWS * 128)     // 2.048M sampling points

__device__ float g_logits[NROWS * NLOGIT];      // off(256) | softmaxed attn(128)
__device__ __nv_bfloat16 g_ahi[NROWS * EMBED];  // A split-hi  [row][k]
__device__ __nv_bfloat16 g_alo[NROWS * EMBED];  // A split-lo
__device__ __nv_bfloat16 g_bhi[NLOGIT * EMBED]; // B^T split-hi [n][k]
__device__ __nv_bfloat16 g_blo[NLOGIT * EMBED]; // B^T split-lo
__device__ float4 g_wq[NPTS];                   // masked, attn-premultiplied weights
__device__ int4   g_meta[NPTS];                 // {base_elem, dx_elem, dy_elem, 0}

// ======================= helpers =======================
__device__ __forceinline__ uint32_t smem_u32(const void* p) {
    uint32_t a;
    asm("{ .reg .u64 t; cvta.to.shared.u64 t, %1; cvt.u32.u64 %0, t; }" : "=r"(a) : "l"(p));
    return a;
}

__device__ __forceinline__ void ldsm4(uint32_t& r0, uint32_t& r1, uint32_t& r2, uint32_t& r3,
                                      uint32_t addr) {
    asm volatile("ldmatrix.sync.aligned.m8n8.x4.shared.b16 {%0,%1,%2,%3}, [%4];"
                 : "=r"(r0), "=r"(r1), "=r"(r2), "=r"(r3) : "r"(addr));
}

__device__ __forceinline__ void mma16816(float* c, const uint32_t* a, const uint32_t* b) {
    asm volatile(
        "mma.sync.aligned.m16n8k16.row.col.f32.bf16.bf16.f32 "
        "{%0,%1,%2,%3}, {%4,%5,%6,%7}, {%8,%9}, {%0,%1,%2,%3};"
        : "+f"(c[0]), "+f"(c[1]), "+f"(c[2]), "+f"(c[3])
        : "r"(a[0]), "r"(a[1]), "r"(a[2]), "r"(a[3]), "r"(b[0]), "r"(b[1]));
}

__device__ __forceinline__ uint32_t pack_bf2(__nv_bfloat16 a, __nv_bfloat16 b) {
    return (uint32_t)__bfloat16_as_ushort(a) | ((uint32_t)__bfloat16_as_ushort(b) << 16);
}

// ======================= conversion kernels =======================
__global__ __launch_bounds__(256)
void conv_a_kernel(const float* __restrict__ q)
{
    const size_t i = ((size_t)blockIdx.x * 256 + threadIdx.x) * 8;
    float4 v0 = __ldg(reinterpret_cast<const float4*>(q + i));
    float4 v1 = __ldg(reinterpret_cast<const float4*>(q + i + 4));
    float v[8] = {v0.x, v0.y, v0.z, v0.w, v1.x, v1.y, v1.z, v1.w};
    __nv_bfloat16 hi[8], lo[8];
    #pragma unroll
    for (int j = 0; j < 8; j++) {
        hi[j] = __float2bfloat16(v[j]);
        lo[j] = __float2bfloat16(v[j] - __bfloat162float(hi[j]));
    }
    uint4 uh, ul;
    uh.x = pack_bf2(hi[0], hi[1]); uh.y = pack_bf2(hi[2], hi[3]);
    uh.z = pack_bf2(hi[4], hi[5]); uh.w = pack_bf2(hi[6], hi[7]);
    ul.x = pack_bf2(lo[0], lo[1]); ul.y = pack_bf2(lo[2], lo[3]);
    ul.z = pack_bf2(lo[4], lo[5]); ul.w = pack_bf2(lo[6], lo[7]);
    *reinterpret_cast<uint4*>(g_ahi + i) = uh;
    *reinterpret_cast<uint4*>(g_alo + i) = ul;
}

__global__ __launch_bounds__(256)
void conv_b_kernel(const float* __restrict__ Woff, const float* __restrict__ Wattn)
{
    const int n = blockIdx.x;    // 0..383 (output column = B^T row)
    const int k = threadIdx.x;   // 0..255
    float x = (n < 256) ? __ldg(Woff + (size_t)k * 256 + n)
                        : __ldg(Wattn + (size_t)k * 128 + (n - 256));
    __nv_bfloat16 h = __float2bfloat16(x);
    g_bhi[(size_t)n * EMBED + k] = h;
    g_blo[(size_t)n * EMBED + k] = __float2bfloat16(x - __bfloat162float(h));
}

// ======================= mma.sync GEMM kernel (unchanged from R7) =======================
#define LDA   72
#define A_HI  0
#define A_LO  18432
#define B_HI  36864
#define B_LO  55296
#define SMT   73728
#define LDD   132

__global__ __launch_bounds__(256)
void mma_gemm_kernel(const float* __restrict__ boff, const float* __restrict__ battn)
{
    extern __shared__ char smem[];
    const int tid  = threadIdx.x;
    const int wid  = tid >> 5;
    const int lane = tid & 31;
    const int bn   = blockIdx.y;
    const int rowg = blockIdx.x * 128;
    const uint32_t sb = smem_u32(smem);

    const int warp_m = (wid >> 1) * 32;
    const int warp_n = (wid & 1) * 64;

    float acc[2][8][4];
    #pragma unroll
    for (int mi = 0; mi < 2; mi++)
        #pragma unroll
        for (int nj = 0; nj < 8; nj++)
            #pragma unroll
            for (int c = 0; c < 4; c++) acc[mi][nj][c] = 0.f;

    for (int kc = 0; kc < 4; kc++) {
        const int k0 = kc * 64;
        __syncthreads();
        #pragma unroll
        for (int r = 0; r < 4; r++) {
            const int s = tid + r * 256;
            const int row = s >> 3, j = s & 7;
            const uint32_t doff = (uint32_t)(row * LDA + j * 8) * 2;
            const size_t asrc = (size_t)(rowg + row) * EMBED + k0 + j * 8;
            const size_t bsrc = (size_t)(bn * 128 + row) * EMBED + k0 + j * 8;
            *reinterpret_cast<uint4*>(smem + A_HI + doff) = *reinterpret_cast<const uint4*>(g_ahi + asrc);
            *reinterpret_cast<uint4*>(smem + A_LO + doff) = *reinterpret_cast<const uint4*>(g_alo + asrc);
            *reinterpret_cast<uint4*>(smem + B_HI + doff) = *reinterpret_cast<const uint4*>(g_bhi + bsrc);
            *reinterpret_cast<uint4*>(smem + B_LO + doff) = *reinterpret_cast<const uint4*>(g_blo + bsrc);
        }
        __syncthreads();

        #pragma unroll
        for (int ks = 0; ks < 4; ks++) {
            const int kk = ks * 16;

            uint32_t ah[2][4], al[2][4];
            const int ar = warp_m + (lane & 15);
            const int ac = kk + ((lane >> 4) << 3);
            #pragma unroll
            for (int mi = 0; mi < 2; mi++) {
                const uint32_t ad = sb + A_HI + (uint32_t)(((ar + mi * 16) * LDA + ac) << 1);
                ldsm4(ah[mi][0], ah[mi][1], ah[mi][2], ah[mi][3], ad);
                ldsm4(al[mi][0], al[mi][1], al[mi][2], al[mi][3], ad + (A_LO - A_HI));
            }

            uint32_t bhf[4][4], blf[4][4];
            const int br = warp_n + (lane & 7) + ((lane >> 4) << 3);
            const int bc = kk + (((lane >> 3) & 1) << 3);
            #pragma unroll
            for (int g = 0; g < 4; g++) {
                const uint32_t bd = sb + B_HI + (uint32_t)(((br + g * 16) * LDA + bc) << 1);
                ldsm4(bhf[g][0], bhf[g][1], bhf[g][2], bhf[g][3], bd);
                ldsm4(blf[g][0], blf[g][1], blf[g][2], blf[g][3], bd + (B_LO - B_HI));
            }

            #pragma unroll
            for (int mi = 0; mi < 2; mi++)
                #pragma unroll
                for (int nj = 0; nj < 8; nj++) {
                    const int g = nj >> 1, o = (nj & 1) * 2;
                    mma16816(acc[mi][nj], ah[mi], &bhf[g][o]);
                    mma16816(acc[mi][nj], ah[mi], &blf[g][o]);
                    mma16816(acc[mi][nj], al[mi], &bhf[g][o]);
                }
        }
    }

    __syncthreads();
    float* sD = reinterpret_cast<float*>(smem);
    #pragma unroll
    for (int mi = 0; mi < 2; mi++)
        #pragma unroll
        for (int nj = 0; nj < 8; nj++) {
            const int r0 = warp_m + mi * 16 + (lane >> 2);
            const int c0 = warp_n + nj * 8 + (lane & 3) * 2;
            *reinterpret_cast<float2*>(sD + r0 * LDD + c0)       = make_float2(acc[mi][nj][0], acc[mi][nj][1]);
            *reinterpret_cast<float2*>(sD + (r0 + 8) * LDD + c0) = make_float2(acc[mi][nj][2], acc[mi][nj][3]);
        }
    __syncthreads();

    const int row = tid >> 1;
    const int cp  = (tid & 1) * 64;
    float* orow = g_logits + (size_t)(rowg + row) * NLOGIT + bn * 128 + cp;

    #pragma unroll
    for (int g4 = 0; g4 < 4; g4++) {
        float f[16];
        #pragma unroll
        for (int j = 0; j < 16; j++) {
            const int c = cp + g4 * 16 + j;
            const float bias = (bn < 2) ? __ldg(boff + bn * 128 + c) : __ldg(battn + c);
            f[j] = sD[row * LDD + c] + bias;
        }
        if (bn == 2) {
            float mx = f[0];
            #pragma unroll
            for (int j = 1; j < 16; j++) mx = fmaxf(mx, f[j]);
            float s = 0.f;
            #pragma unroll
            for (int j = 0; j < 16; j++) { f[j] = __expf(f[j] - mx); s += f[j]; }
            const float rs = __fdividef(1.f, s);
            #pragma unroll
            for (int j = 0; j < 16; j++) f[j] *= rs;
        }
        #pragma unroll
        for (int j = 0; j < 16; j += 4)
            *reinterpret_cast<float4*>(orow + g4 * 16 + j) = make_float4(f[j], f[j+1], f[j+2], f[j+3]);
    }
}

// ======================= point precompute kernel =======================
// one thread per sampling point (row, h, p). Emits validity-masked,
// attention-premultiplied bilinear weights and a clamped base + dx/dy element
// steps such that all 4 corner loads are always in-range (weights carry the
// boundary semantics).
__global__ __launch_bounds__(256)
void prep_kernel(const float* __restrict__ refp)
{
    constexpr int cW[4]  = {100, 50, 25, 13};
    constexpr int cVS[4] = {0, 10000, 12500, 13125};

    const int idx = blockIdx.x * 256 + threadIdx.x;   // 0 .. NPTS-1
    const int row = idx >> 7;
    const int hp  = idx & 127;
    const int p   = hp & 15;
    const int lvl = p >> 2;

    const float* lg = g_logits + (size_t)row * NLOGIT;
    const float2 off = *reinterpret_cast<const float2*>(lg + 2 * hp);
    const float  ap  = __ldg(lg + 256 + hp);
    const float4 rp  = __ldg(reinterpret_cast<const float4*>(refp) + row);

    const int   W  = cW[lvl];
    const float Wf = (float)W;

    const float px = fmaf(fmaf(off.x, 0.125f * rp.z, rp.x), Wf, -0.5f);
    const float py = fmaf(fmaf(off.y, 0.125f * rp.w, rp.y), Wf, -0.5f);
    const float fx0 = floorf(px), fy0 = floorf(py);
    const float fx = px - fx0,    fy = py - fy0;
    const int x0 = (int)fx0, y0 = (int)fy0;

    const bool xin0 = (unsigned)x0       < (unsigned)W;
    const bool xin1 = (unsigned)(x0 + 1) < (unsigned)W;
    const bool yin0 = (unsigned)y0       < (unsigned)W;   // H == W (square levels)
    const bool yin1 = (unsigned)(y0 + 1) < (unsigned)W;

    const float gx = 1.f - fx, gy = 1.f - fy;
    float4 w;
    w.x = (xin0 && yin0) ? ap * gx * gy : 0.f;
    w.y = (xin1 && yin0) ? ap * fx * gy : 0.f;
    w.z = (xin0 && yin1) ? ap * gx * fy : 0.f;
    w.w = (xin1 && yin1) ? ap * fx * fy : 0.f;

    const int x0c = min(max(x0, 0),     W - 1);
    const int x1c = min(max(x0 + 1, 0), W - 1);
    const int y0c = min(max(y0, 0),     W - 1);
    const int y1c = min(max(y0 + 1, 0), W - 1);

    int4 mt;
    mt.x = (cVS[lvl] + y0c * W + x0c) * EMBED;   // base element offset (always in-range)
    mt.y = (x1c - x0c) * EMBED;                  // dx step (0 or 256)
    mt.z = (y1c - y0c) * W * EMBED;              // dy step (0 or W*256)
    mt.w = 0;

    g_wq[idx]   = w;
    g_meta[idx] = mt;
}

// ======================= gather kernel (load-only) =======================
// one warp per (b, h, q): psub = lane>>3 picks one of 4 parallel points,
// dgrp = lane&7 covers the 32-dim head with float4 loads. No predication,
// no coordinate math — everything comes from g_wq / g_meta.
__global__ __launch_bounds__(256, 6)
void sample_kernel(const float* __restrict__ value,
                   float* __restrict__ out)
{
    const int warp = (blockIdx.x << 3) + (threadIdx.x >> 5);
    const int lane = threadIdx.x & 31;

    const int q  = warp % LQ_;
    const int bh = warp / LQ_;
    const int b  = bh >> 3;
    const int h  = bh & 7;
    const int row = b * LQ_ + q;

    const int psub = lane >> 3;
    const int dgrp = lane & 7;

    const float4* wqp = g_wq   + (size_t)row * 128 + h * 16 + psub;
    const int4*   mtp = g_meta + (size_t)row * 128 + h * 16 + psub;
    const float*  vb  = value + (size_t)b * LV_ * EMBED + h * HDIM + dgrp * 4;

    float4 acc0 = make_float4(0.f, 0.f, 0.f, 0.f);
    float4 acc1 = acc0;

    #pragma unroll
    for (int it = 0; it < 4; it++) {
        const float4 w  = __ldg(wqp + (it << 2));
        const int4   mt = __ldg(mtp + (it << 2));

        const float* vl = vb + mt.x;
        const float4 v00 = *reinterpret_cast<const float4*>(vl);
        const float4 v10 = *reinterpret_cast<const float4*>(vl + mt.y);
        const float4 v01 = *reinterpret_cast<const float4*>(vl + mt.z);
        const float4 v11 = *reinterpret_cast<const float4*>(vl + mt.z + mt.y);

        float4& acc = (it & 1) ? acc1 : acc0;
        acc.x = fmaf(w.x, v00.x, fmaf(w.y, v10.x, fmaf(w.z, v01.x, fmaf(w.w, v11.x, acc.x))));
        acc.y = fmaf(w.x, v00.y, fmaf(w.y, v10.y, fmaf(w.z, v01.y, fmaf(w.w, v11.y, acc.y))));
        acc.z = fmaf(w.x, v00.z, fmaf(w.y, v10.z, fmaf(w.z, v01.z, fmaf(w.w, v11.z, acc.z))));
        acc.w = fmaf(w.x, v00.w, fmaf(w.y, v10.w, fmaf(w.z, v01.w, fmaf(w.w, v11.w, acc.w))));
    }

    float4 acc;
    acc.x = acc0.x + acc1.x;
    acc.y = acc0.y + acc1.y;
    acc.z = acc0.z + acc1.z;
    acc.w = acc0.w + acc1.w;

    #pragma unroll
    for (int o = 8; o <= 16; o <<= 1) {
        acc.x += __shfl_xor_sync(0xffffffffu, acc.x, o);
        acc.y += __shfl_xor_sync(0xffffffffu, acc.y, o);
        acc.z += __shfl_xor_sync(0xffffffffu, acc.z, o);
        acc.w += __shfl_xor_sync(0xffffffffu, acc.w, o);
    }

    if (psub == 0) {
        *reinterpret_cast<float4*>(out + (size_t)row * EMBED + h * HDIM + dgrp * 4) = acc;
    }
}

// ---------------- launch ----------------
extern "C" void kernel_launch(void* const* d_in, const int* in_sizes, int n_in,
                              void* d_out, int out_size)
{
    (void)in_sizes; (void)n_in; (void)out_size;
    const float* query = (const float*)d_in[0];
    const float* refp  = (const float*)d_in[1];
    const float* value = (const float*)d_in[2];
    // d_in[3] = value_spatial_shapes (int64) — hardcoded
    const float* Woff  = (const float*)d_in[4];
    const float* boff  = (const float*)d_in[5];
    const float* Wattn = (const float*)d_in[6];
    const float* battn = (const float*)d_in[7];
    float* out = (float*)d_out;

    static bool attr_set = false;
    if (!attr_set) {
        cudaFuncSetAttribute(mma_gemm_kernel,
                             cudaFuncAttributeMaxDynamicSharedMemorySize, SMT);
        attr_set = true;
    }

    conv_a_kernel<<<(NROWS * EMBED / 8) / 256, 256>>>(query);
    conv_b_kernel<<<NLOGIT, 256>>>(Woff, Wattn);
    mma_gemm_kernel<<<dim3(NROWS / 128, 3), 256, SMT>>>(boff, battn);
    prep_kernel<<<NPTS / 256, 256>>>(refp);
    sample_kernel<<<(BS_ * NHEADS * LQ_) / 8, 256>>>(value, out);
}